// round 2
// baseline (speedup 1.0000x reference)
#include <cuda_runtime.h>
#include <math.h>

// Problem constants: N rows up to 100000, MUL=128, x row = 512 floats.
#define MAXN 100000
#define SQ2F 1.41421356237309515f

// Scratch (allocation-free rule: __device__ globals). ~1.07 GB total.
__device__ float g_scal [(size_t)MAXN * 384];      // scal = [s, s^2, |v|^2]; later gated in-place
__device__ float g_h    [(size_t)MAXN * 384];      // h = silu(scal @ W1)
__device__ float g_gates[(size_t)MAXN * 640];      // silu(h @ W2[:, :640])  (cols 640:768 are dead)
__device__ float g_vg   [(size_t)MAXN * 256 * 3];  // gated vecs, 3 planes of [n,256]
__device__ float g_outs [(size_t)MAXN * 128];      // scal_gated @ lin_ws
__device__ float g_outv [(size_t)MAXN * 128 * 3];  // vg_i @ lin_wv, 3 planes of [n,128]

__device__ __forceinline__ float silu_f(float v) { return v / (1.0f + expf(-v)); }

// ---------------------------------------------------------------------------
// K1: build scal[n,384] = [s, s*s, vx^2+vy^2+vz^2]
// ---------------------------------------------------------------------------
__global__ void prep_scal_kernel(const float* __restrict__ x, float* __restrict__ scal, int n) {
    int idx = blockIdx.x * blockDim.x + threadIdx.x;
    if (idx >= n * 128) return;
    int row = idx >> 7;
    int u = idx & 127;
    const float* xr = x + (size_t)row * 512;
    float s  = xr[u];
    float v0 = xr[128 + u * 3 + 0];
    float v1 = xr[128 + u * 3 + 1];
    float v2 = xr[128 + u * 3 + 2];
    float* sr = scal + (size_t)row * 384;
    sr[u]       = s;
    sr[128 + u] = s * s;
    sr[256 + u] = v0 * v0 + v1 * v1 + v2 * v2;
}

// ---------------------------------------------------------------------------
// Generic fp32 tiled GEMM: C[M,N] = A[M,K] @ B[K,N]  (B row-major, ldb >= N)
// BM=128, BN=64, BK=16, 256 threads, 8x4 register tile. Optional silu epilogue.
// blockIdx.z batches over independent A/C planes (for the 3-component einsum).
// Requires: N (grid.y*64) multiple of 64, K multiple of 16, 16B-aligned ptrs.
// ---------------------------------------------------------------------------
template <bool SILU>
__global__ __launch_bounds__(256) void gemm_kernel(
    const float* __restrict__ A, int lda, long long bsA,
    const float* __restrict__ B, int ldb,
    float* __restrict__ C, int ldc, long long bsC,
    int M, int K)
{
    __shared__ float As[16][128];   // transposed: As[k][m]
    __shared__ float Bs[16][64];

    A += (size_t)blockIdx.z * bsA;
    C += (size_t)blockIdx.z * bsC;

    const int tid = threadIdx.x;
    const int ty = tid >> 4;        // 0..15 -> row group (8 rows each)
    const int tx = tid & 15;        // 0..15 -> col group (4 cols each)
    const int rowBase = blockIdx.x * 128;
    const int colBase = blockIdx.y * 64;

    float acc[8][4];
#pragma unroll
    for (int i = 0; i < 8; i++)
#pragma unroll
        for (int j = 0; j < 4; j++) acc[i][j] = 0.0f;

    for (int k0 = 0; k0 < K; k0 += 16) {
        // Load A tile (128x16) as float4, store transposed into As[k][m]
#pragma unroll
        for (int it = 0; it < 2; it++) {
            int f = it * 256 + tid;          // 0..511
            int r = f >> 2;                  // 0..127
            int c = (f & 3) * 4;             // 0,4,8,12
            int gr = rowBase + r;
            float4 va = make_float4(0.f, 0.f, 0.f, 0.f);
            if (gr < M)
                va = *reinterpret_cast<const float4*>(A + (size_t)gr * lda + k0 + c);
            As[c + 0][r] = va.x;
            As[c + 1][r] = va.y;
            As[c + 2][r] = va.z;
            As[c + 3][r] = va.w;
        }
        // Load B tile (16x64) as float4 (N assumed in-bounds: grid.y*64 <= N)
        {
            int kb = tid >> 4;               // 0..15
            int nb = (tid & 15) * 4;         // 0..60
            float4 vb = *reinterpret_cast<const float4*>(
                B + (size_t)(k0 + kb) * ldb + colBase + nb);
            *reinterpret_cast<float4*>(&Bs[kb][nb]) = vb;
        }
        __syncthreads();

#pragma unroll
        for (int k = 0; k < 16; k++) {
            float4 a0 = *reinterpret_cast<const float4*>(&As[k][ty * 8]);
            float4 a1 = *reinterpret_cast<const float4*>(&As[k][ty * 8 + 4]);
            float4 b  = *reinterpret_cast<const float4*>(&Bs[k][tx * 4]);
            float ar[8] = {a0.x, a0.y, a0.z, a0.w, a1.x, a1.y, a1.z, a1.w};
            float br[4] = {b.x, b.y, b.z, b.w};
#pragma unroll
            for (int i = 0; i < 8; i++)
#pragma unroll
                for (int j = 0; j < 4; j++)
                    acc[i][j] = fmaf(ar[i], br[j], acc[i][j]);
        }
        __syncthreads();
    }

    // Epilogue
#pragma unroll
    for (int i = 0; i < 8; i++) {
        int gr = rowBase + ty * 8 + i;
        if (gr < M) {
            float4 o;
            if (SILU) {
                o.x = silu_f(acc[i][0]);
                o.y = silu_f(acc[i][1]);
                o.z = silu_f(acc[i][2]);
                o.w = silu_f(acc[i][3]);
            } else {
                o.x = acc[i][0]; o.y = acc[i][1]; o.z = acc[i][2]; o.w = acc[i][3];
            }
            *reinterpret_cast<float4*>(C + (size_t)gr * ldc + colBase + tx * 4) = o;
        }
    }
}

// ---------------------------------------------------------------------------
// K4: gate scal in place (scal *= gs) and build gated vec planes:
//   vg_i[row][u]       = v[u][i] * gates[384+u]                (u < 128)
//   vg_i[row][128+u]   = sqrt(2)*s[u]*v[u][i] * gates[512+u]
// ---------------------------------------------------------------------------
__global__ void gate_prep_kernel(const float* __restrict__ x, const float* __restrict__ gates,
                                 float* __restrict__ scal, float* __restrict__ vg, int n) {
    int idx = blockIdx.x * blockDim.x + threadIdx.x;
    if (idx >= n * 384) return;
    int row = idx / 384;
    int j = idx - row * 384;
    const float* g = gates + (size_t)row * 640;
    scal[idx] = scal[idx] * g[j];
    if (j < 128) {
        int u = j;
        const float* xr = x + (size_t)row * 512;
        float s  = xr[u];
        float g1 = g[384 + u];
        float c2 = SQ2F * s * g[512 + u];
#pragma unroll
        for (int i = 0; i < 3; i++) {
            float vi = xr[128 + u * 3 + i];
            float* vgp = vg + ((size_t)i * n + row) * 256;
            vgp[u]       = vi * g1;
            vgp[128 + u] = vi * c2;
        }
    }
}

// ---------------------------------------------------------------------------
// K7: residuals + scalar layernorm + vector RMS norm, write output [n,512].
// One warp per row; lane handles channels {lane, lane+32, lane+64, lane+96}.
// ---------------------------------------------------------------------------
__global__ void finalize_kernel(const float* __restrict__ x, const float* __restrict__ outs,
                                const float* __restrict__ outv, float* __restrict__ out, int n) {
    int gw = (int)((blockIdx.x * blockDim.x + threadIdx.x) >> 5);
    int lane = threadIdx.x & 31;
    if (gw >= n) return;
    const float* xr = x + (size_t)gw * 512;
    float* orow = out + (size_t)gw * 512;

    // scalar channel: out_s = outs + s, center, rms-normalize
    float so[4];
    float sum = 0.f;
#pragma unroll
    for (int t = 0; t < 4; t++) {
        int u = lane + 32 * t;
        so[t] = outs[(size_t)gw * 128 + u] + xr[u];
        sum += so[t];
    }
#pragma unroll
    for (int o = 16; o > 0; o >>= 1) sum += __shfl_xor_sync(0xffffffffu, sum, o);
    float mean = sum * (1.0f / 128.0f);
    float ssum = 0.f;
#pragma unroll
    for (int t = 0; t < 4; t++) {
        so[t] -= mean;
        ssum += so[t] * so[t];
    }
#pragma unroll
    for (int o = 16; o > 0; o >>= 1) ssum += __shfl_xor_sync(0xffffffffu, ssum, o);
    float inv = 1.0f / (sqrtf(ssum * (1.0f / 128.0f)) + 1e-6f);
#pragma unroll
    for (int t = 0; t < 4; t++) orow[lane + 32 * t] = so[t] * inv;

    // vector channel: out_v = outv + v, RMS over all (u,i)
    float vo[4][3];
    float vs = 0.f;
#pragma unroll
    for (int t = 0; t < 4; t++) {
        int u = lane + 32 * t;
#pragma unroll
        for (int i = 0; i < 3; i++) {
            vo[t][i] = outv[((size_t)i * n + gw) * 128 + u] + xr[128 + u * 3 + i];
            vs += vo[t][i] * vo[t][i];
        }
    }
#pragma unroll
    for (int o = 16; o > 0; o >>= 1) vs += __shfl_xor_sync(0xffffffffu, vs, o);
    float vinv = 1.0f / (sqrtf(vs * (1.0f / 128.0f)) + 1e-6f);
#pragma unroll
    for (int t = 0; t < 4; t++) {
        int u = lane + 32 * t;
#pragma unroll
        for (int i = 0; i < 3; i++)
            orow[128 + u * 3 + i] = vo[t][i] * vinv;
    }
}

// ---------------------------------------------------------------------------
extern "C" void kernel_launch(void* const* d_in, const int* in_sizes, int n_in,
                              void* d_out, int out_size) {
    const float* x  = (const float*)d_in[0];
    const float* W1 = (const float*)d_in[1];   // [384,384]
    const float* W2 = (const float*)d_in[2];   // [384,768] (cols 640:768 dead)
    const float* Ws = (const float*)d_in[3];   // [384,128]
    const float* Wv = (const float*)d_in[4];   // [256,128]
    float* out = (float*)d_out;
    int n = in_sizes[0] / 512;

    float *scal, *h, *gates, *vg, *outs, *outv;
    cudaGetSymbolAddress((void**)&scal,  g_scal);
    cudaGetSymbolAddress((void**)&h,     g_h);
    cudaGetSymbolAddress((void**)&gates, g_gates);
    cudaGetSymbolAddress((void**)&vg,    g_vg);
    cudaGetSymbolAddress((void**)&outs,  g_outs);
    cudaGetSymbolAddress((void**)&outv,  g_outv);

    int mblocks = (n + 127) / 128;

    // K1: scal features
    prep_scal_kernel<<<(n * 128 + 255) / 256, 256>>>(x, scal, n);

    // G1: h = silu(scal @ W1)   [n,384] = [n,384]x[384,384]
    dim3 g1(mblocks, 384 / 64, 1);
    gemm_kernel<true><<<g1, 256>>>(scal, 384, 0LL, W1, 384, h, 384, 0LL, n, 384);

    // G2: gates = silu(h @ W2[:, :640])   [n,640] = [n,384]x[384,640] (ldb=768)
    dim3 g2(mblocks, 640 / 64, 1);
    gemm_kernel<true><<<g2, 256>>>(h, 384, 0LL, W2, 768, gates, 640, 0LL, n, 384);

    // K4: gate scal in-place, build vg planes
    gate_prep_kernel<<<(n * 384 + 255) / 256, 256>>>(x, gates, scal, vg, n);

    // G5: outs = scal_gated @ Ws   [n,128] = [n,384]x[384,128]
    dim3 g5(mblocks, 128 / 64, 1);
    gemm_kernel<false><<<g5, 256>>>(scal, 384, 0LL, Ws, 128, outs, 128, 0LL, n, 384);

    // G6: outv_i = vg_i @ Wv   3 x ([n,128] = [n,256]x[256,128]) batched over z
    dim3 g6(mblocks, 128 / 64, 3);
    gemm_kernel<false><<<g6, 256>>>(vg, 256, (long long)n * 256, Wv, 128,
                                    outv, 128, (long long)n * 128, n, 256);

    // K7: residual + norms + output
    finalize_kernel<<<(n + 7) / 8, 256>>>(x, outs, outv, out, n);
}

// round 3
// speedup vs baseline: 1.9270x; 1.9270x over previous
#include <cuda_runtime.h>
#include <math.h>

// Problem constants: N rows up to 100000, MUL=128, x row = 512 floats.
#define MAXN 100000
#define SQ2F 1.41421356237309515f

// Scratch (allocation-free rule: __device__ globals).
__device__ float g_scal [(size_t)MAXN * 384];      // scal = [s, s^2, |v|^2]; later gated in-place
__device__ float g_h    [(size_t)MAXN * 384];      // h = silu(scal @ W1)
__device__ float g_gates[(size_t)MAXN * 640];      // silu(h @ W2[:, :640])  (cols 640:768 are dead)
__device__ float g_vg   [(size_t)MAXN * 256 * 3];  // gated vecs, 3 planes of [n,256]
__device__ float g_outs [(size_t)MAXN * 128];      // scal_gated @ lin_ws
__device__ float g_outv [(size_t)MAXN * 128 * 3];  // vg_i @ lin_wv, 3 planes of [n,128]

__device__ __forceinline__ float silu_f(float v) { return v / (1.0f + expf(-v)); }

__device__ __forceinline__ unsigned f2tf32(float x) {
    unsigned u;
    asm("cvt.rna.tf32.f32 %0, %1;" : "=r"(u) : "f"(x));
    return u;
}

// ---------------------------------------------------------------------------
// K1: build scal[n,384] = [s, s*s, vx^2+vy^2+vz^2]
// ---------------------------------------------------------------------------
__global__ void prep_scal_kernel(const float* __restrict__ x, float* __restrict__ scal, int n) {
    int idx = blockIdx.x * blockDim.x + threadIdx.x;
    if (idx >= n * 128) return;
    int row = idx >> 7;
    int u = idx & 127;
    const float* xr = x + (size_t)row * 512;
    float s  = xr[u];
    float v0 = xr[128 + u * 3 + 0];
    float v1 = xr[128 + u * 3 + 1];
    float v2 = xr[128 + u * 3 + 2];
    float* sr = scal + (size_t)row * 384;
    sr[u]       = s;
    sr[128 + u] = s * s;
    sr[256 + u] = v0 * v0 + v1 * v1 + v2 * v2;
}

// ---------------------------------------------------------------------------
// TF32 tensor-core GEMM: C[M,N] = A[M,K] @ B[K,N]  (both row-major)
// Block tile 128x64, BK=16, 256 threads = 8 warps in 4(M) x 2(N) grid,
// warp tile 32x32 = 2x4 m16n8k8 atoms. fp32 accumulate. Optional silu.
// blockIdx.z batches independent A/C planes.
// Requires: grid.y*64 <= N-capacity of B (ldb), K % 16 == 0, 16B alignment.
// ---------------------------------------------------------------------------
template <bool SILU>
__global__ __launch_bounds__(256) void gemm_tf32_kernel(
    const float* __restrict__ A, int lda, long long bsA,
    const float* __restrict__ B, int ldb,
    float* __restrict__ C, int ldc, long long bsC,
    int M, int K)
{
    // Padded strides (mod 32 == 8) -> conflict-free fragment loads.
    __shared__ unsigned As[16][136];   // As[k][m], tf32 bits
    __shared__ unsigned Bs[16][72];    // Bs[k][n], tf32 bits

    A += (size_t)blockIdx.z * bsA;
    C += (size_t)blockIdx.z * bsC;

    const int tid  = threadIdx.x;
    const int lane = tid & 31;
    const int w    = tid >> 5;
    const int wm   = (w & 3) * 32;     // warp M offset in tile
    const int wn   = (w >> 2) * 32;    // warp N offset in tile
    const int g    = lane >> 2;        // group id (0..7)
    const int tg   = lane & 3;         // thread in group (0..3)
    const int rowBase = blockIdx.x * 128;
    const int colBase = blockIdx.y * 64;

    float acc[2][4][4];
#pragma unroll
    for (int mt = 0; mt < 2; mt++)
#pragma unroll
        for (int nt = 0; nt < 4; nt++)
#pragma unroll
            for (int i = 0; i < 4; i++) acc[mt][nt][i] = 0.0f;

    for (int k0 = 0; k0 < K; k0 += 16) {
        // Load A tile (128x16) as float4, convert to tf32, store transposed As[k][m]
#pragma unroll
        for (int it = 0; it < 2; it++) {
            int f = it * 256 + tid;          // 0..511
            int r = f >> 2;                  // 0..127
            int c = (f & 3) * 4;             // 0,4,8,12
            int gr = rowBase + r;
            float4 va = make_float4(0.f, 0.f, 0.f, 0.f);
            if (gr < M)
                va = *reinterpret_cast<const float4*>(A + (size_t)gr * lda + k0 + c);
            As[c + 0][r] = f2tf32(va.x);
            As[c + 1][r] = f2tf32(va.y);
            As[c + 2][r] = f2tf32(va.z);
            As[c + 3][r] = f2tf32(va.w);
        }
        // Load B tile (16x64)
        {
            int kb = tid >> 4;               // 0..15
            int nb = (tid & 15) * 4;         // 0..60
            float4 vb = *reinterpret_cast<const float4*>(
                B + (size_t)(k0 + kb) * ldb + colBase + nb);
            Bs[kb][nb + 0] = f2tf32(vb.x);
            Bs[kb][nb + 1] = f2tf32(vb.y);
            Bs[kb][nb + 2] = f2tf32(vb.z);
            Bs[kb][nb + 3] = f2tf32(vb.w);
        }
        __syncthreads();

        unsigned a[2][2][4];   // [kf][mt][4]
        unsigned b[2][4][2];   // [kf][nt][2]
#pragma unroll
        for (int kf = 0; kf < 2; kf++) {
            const int k = kf * 8;
#pragma unroll
            for (int mt = 0; mt < 2; mt++) {
                const int m = wm + mt * 16 + g;
                a[kf][mt][0] = As[k + tg][m];
                a[kf][mt][1] = As[k + tg][m + 8];
                a[kf][mt][2] = As[k + tg + 4][m];
                a[kf][mt][3] = As[k + tg + 4][m + 8];
            }
#pragma unroll
            for (int nt = 0; nt < 4; nt++) {
                const int nn = wn + nt * 8 + g;
                b[kf][nt][0] = Bs[k + tg][nn];
                b[kf][nt][1] = Bs[k + tg + 4][nn];
            }
        }
#pragma unroll
        for (int kf = 0; kf < 2; kf++)
#pragma unroll
            for (int mt = 0; mt < 2; mt++)
#pragma unroll
                for (int nt = 0; nt < 4; nt++) {
                    asm volatile(
                        "mma.sync.aligned.m16n8k8.row.col.f32.tf32.tf32.f32 "
                        "{%0,%1,%2,%3}, {%4,%5,%6,%7}, {%8,%9}, {%0,%1,%2,%3};\n"
                        : "+f"(acc[mt][nt][0]), "+f"(acc[mt][nt][1]),
                          "+f"(acc[mt][nt][2]), "+f"(acc[mt][nt][3])
                        : "r"(a[kf][mt][0]), "r"(a[kf][mt][1]),
                          "r"(a[kf][mt][2]), "r"(a[kf][mt][3]),
                          "r"(b[kf][nt][0]), "r"(b[kf][nt][1]));
                }
        __syncthreads();
    }

    // Epilogue: c0 at (row g, col 2*tg), c1 col+1, c2/c3 at row g+8.
#pragma unroll
    for (int mt = 0; mt < 2; mt++) {
        int r0 = rowBase + wm + mt * 16 + g;
#pragma unroll
        for (int nt = 0; nt < 4; nt++) {
            int c0 = colBase + wn + nt * 8 + 2 * tg;
            float2 lo = make_float2(acc[mt][nt][0], acc[mt][nt][1]);
            float2 hi = make_float2(acc[mt][nt][2], acc[mt][nt][3]);
            if (SILU) {
                lo.x = silu_f(lo.x); lo.y = silu_f(lo.y);
                hi.x = silu_f(hi.x); hi.y = silu_f(hi.y);
            }
            if (r0 < M)
                *reinterpret_cast<float2*>(C + (size_t)r0 * ldc + c0) = lo;
            if (r0 + 8 < M)
                *reinterpret_cast<float2*>(C + (size_t)(r0 + 8) * ldc + c0) = hi;
        }
    }
}

// ---------------------------------------------------------------------------
// K4: gate scal in place (scal *= gs) and build gated vec planes:
//   vg_i[row][u]       = v[u][i] * gates[384+u]                (u < 128)
//   vg_i[row][128+u]   = sqrt(2)*s[u]*v[u][i] * gates[512+u]
// ---------------------------------------------------------------------------
__global__ void gate_prep_kernel(const float* __restrict__ x, const float* __restrict__ gates,
                                 float* __restrict__ scal, float* __restrict__ vg, int n) {
    int idx = blockIdx.x * blockDim.x + threadIdx.x;
    if (idx >= n * 384) return;
    int row = idx / 384;
    int j = idx - row * 384;
    const float* g = gates + (size_t)row * 640;
    scal[idx] = scal[idx] * g[j];
    if (j < 128) {
        int u = j;
        const float* xr = x + (size_t)row * 512;
        float s  = xr[u];
        float g1 = g[384 + u];
        float c2 = SQ2F * s * g[512 + u];
#pragma unroll
        for (int i = 0; i < 3; i++) {
            float vi = xr[128 + u * 3 + i];
            float* vgp = vg + ((size_t)i * n + row) * 256;
            vgp[u]       = vi * g1;
            vgp[128 + u] = vi * c2;
        }
    }
}

// ---------------------------------------------------------------------------
// K7: residuals + scalar layernorm + vector RMS norm, write output [n,512].
// ---------------------------------------------------------------------------
__global__ void finalize_kernel(const float* __restrict__ x, const float* __restrict__ outs,
                                const float* __restrict__ outv, float* __restrict__ out, int n) {
    int gw = (int)((blockIdx.x * blockDim.x + threadIdx.x) >> 5);
    int lane = threadIdx.x & 31;
    if (gw >= n) return;
    const float* xr = x + (size_t)gw * 512;
    float* orow = out + (size_t)gw * 512;

    float so[4];
    float sum = 0.f;
#pragma unroll
    for (int t = 0; t < 4; t++) {
        int u = lane + 32 * t;
        so[t] = outs[(size_t)gw * 128 + u] + xr[u];
        sum += so[t];
    }
#pragma unroll
    for (int o = 16; o > 0; o >>= 1) sum += __shfl_xor_sync(0xffffffffu, sum, o);
    float mean = sum * (1.0f / 128.0f);
    float ssum = 0.f;
#pragma unroll
    for (int t = 0; t < 4; t++) {
        so[t] -= mean;
        ssum += so[t] * so[t];
    }
#pragma unroll
    for (int o = 16; o > 0; o >>= 1) ssum += __shfl_xor_sync(0xffffffffu, ssum, o);
    float inv = 1.0f / (sqrtf(ssum * (1.0f / 128.0f)) + 1e-6f);
#pragma unroll
    for (int t = 0; t < 4; t++) orow[lane + 32 * t] = so[t] * inv;

    float vo[4][3];
    float vs = 0.f;
#pragma unroll
    for (int t = 0; t < 4; t++) {
        int u = lane + 32 * t;
#pragma unroll
        for (int i = 0; i < 3; i++) {
            vo[t][i] = outv[((size_t)i * n + gw) * 128 + u] + xr[128 + u * 3 + i];
            vs += vo[t][i] * vo[t][i];
        }
    }
#pragma unroll
    for (int o = 16; o > 0; o >>= 1) vs += __shfl_xor_sync(0xffffffffu, vs, o);
    float vinv = 1.0f / (sqrtf(vs * (1.0f / 128.0f)) + 1e-6f);
#pragma unroll
    for (int t = 0; t < 4; t++) {
        int u = lane + 32 * t;
#pragma unroll
        for (int i = 0; i < 3; i++)
            orow[128 + u * 3 + i] = vo[t][i] * vinv;
    }
}

// ---------------------------------------------------------------------------
extern "C" void kernel_launch(void* const* d_in, const int* in_sizes, int n_in,
                              void* d_out, int out_size) {
    const float* x  = (const float*)d_in[0];
    const float* W1 = (const float*)d_in[1];   // [384,384]
    const float* W2 = (const float*)d_in[2];   // [384,768] (cols 640:768 dead)
    const float* Ws = (const float*)d_in[3];   // [384,128]
    const float* Wv = (const float*)d_in[4];   // [256,128]
    float* out = (float*)d_out;
    int n = in_sizes[0] / 512;

    float *scal, *h, *gates, *vg, *outs, *outv;
    cudaGetSymbolAddress((void**)&scal,  g_scal);
    cudaGetSymbolAddress((void**)&h,     g_h);
    cudaGetSymbolAddress((void**)&gates, g_gates);
    cudaGetSymbolAddress((void**)&vg,    g_vg);
    cudaGetSymbolAddress((void**)&outs,  g_outs);
    cudaGetSymbolAddress((void**)&outv,  g_outv);

    int mblocks = (n + 127) / 128;

    // K1: scal features
    prep_scal_kernel<<<(n * 128 + 255) / 256, 256>>>(x, scal, n);

    // G1: h = silu(scal @ W1)   [n,384] = [n,384]x[384,384]
    dim3 g1(mblocks, 384 / 64, 1);
    gemm_tf32_kernel<true><<<g1, 256>>>(scal, 384, 0LL, W1, 384, h, 384, 0LL, n, 384);

    // G2: gates = silu(h @ W2[:, :640])   [n,640] = [n,384]x[384,640] (ldb=768)
    dim3 g2(mblocks, 640 / 64, 1);
    gemm_tf32_kernel<true><<<g2, 256>>>(h, 384, 0LL, W2, 768, gates, 640, 0LL, n, 384);

    // K4: gate scal in-place, build vg planes
    gate_prep_kernel<<<(n * 384 + 255) / 256, 256>>>(x, gates, scal, vg, n);

    // G5: outs = scal_gated @ Ws   [n,128] = [n,384]x[384,128]
    dim3 g5(mblocks, 128 / 64, 1);
    gemm_tf32_kernel<false><<<g5, 256>>>(scal, 384, 0LL, Ws, 128, outs, 128, 0LL, n, 384);

    // G6: outv_i = vg_i @ Wv   3 x ([n,128] = [n,256]x[256,128]) batched over z
    dim3 g6(mblocks, 128 / 64, 3);
    gemm_tf32_kernel<false><<<g6, 256>>>(vg, 256, (long long)n * 256, Wv, 128,
                                         outv, 128, (long long)n * 128, n, 256);

    // K7: residual + norms + output
    finalize_kernel<<<(n + 7) / 8, 256>>>(x, outs, outv, out, n);
}

// round 5
// speedup vs baseline: 2.4735x; 1.2836x over previous
#include <cuda_runtime.h>
#include <math.h>
#include <stdint.h>

// Problem constants: N rows up to 100000, MUL=128, x row = 512 floats.
#define MAXN 100000
#define SQ2F 1.41421356237309515f

// Scratch (allocation-free rule: __device__ globals).
__device__ float g_scal [(size_t)MAXN * 384];
__device__ float g_h    [(size_t)MAXN * 384];
__device__ float g_gates[(size_t)MAXN * 640];
__device__ float g_vg   [(size_t)MAXN * 256 * 3];
__device__ float g_outs [(size_t)MAXN * 128];
__device__ float g_outv [(size_t)MAXN * 128 * 3];
// Packed (transposed to [N,K], tf32-rounded) weights.
__device__ float g_w1p[384 * 384];
__device__ float g_w2p[640 * 384];
__device__ float g_wsp[128 * 384];
__device__ float g_wvp[128 * 256];

__device__ __forceinline__ float silu_f(float v) { return v / (1.0f + expf(-v)); }

__device__ __forceinline__ float rna_tf32(float x) {
    unsigned u;
    asm("cvt.rna.tf32.f32 %0, %1;" : "=r"(u) : "f"(x));
    return __uint_as_float(u);
}

__device__ __forceinline__ uint32_t smem_u32(const void* p) {
    uint32_t a;
    asm("{ .reg .u64 t; cvta.to.shared.u64 t, %1; cvt.u32.u64 %0, t; }" : "=r"(a) : "l"(p));
    return a;
}

__device__ __forceinline__ void cp16(uint32_t dst, const void* src, int sz) {
    asm volatile("cp.async.cg.shared.global [%0], [%1], 16, %2;"
                 :: "r"(dst), "l"(src), "r"(sz) : "memory");
}

// ---------------------------------------------------------------------------
// Weight pack: Wp[n*K + k] = rna_tf32(W[k*ldw + n]); keep first Ncols columns.
// ---------------------------------------------------------------------------
__global__ void pack_w_kernel(const float* __restrict__ W, float* __restrict__ Wp,
                              int K, int Ncols, int ldw) {
    int idx = blockIdx.x * blockDim.x + threadIdx.x;
    if (idx >= Ncols * K) return;
    int n = idx / K;
    int k = idx - n * K;
    Wp[idx] = rna_tf32(W[(size_t)k * ldw + n]);
}

// ---------------------------------------------------------------------------
// K1: scal[n,384] = [s, s*s, |v|^2], tf32-rounded (pre-rounded GEMM input).
// ---------------------------------------------------------------------------
__global__ void prep_scal_kernel(const float* __restrict__ x, float* __restrict__ scal, int n) {
    int idx = blockIdx.x * blockDim.x + threadIdx.x;
    if (idx >= n * 128) return;
    int row = idx >> 7;
    int u = idx & 127;
    const float* xr = x + (size_t)row * 512;
    float s  = xr[u];
    float v0 = xr[128 + u * 3 + 0];
    float v1 = xr[128 + u * 3 + 1];
    float v2 = xr[128 + u * 3 + 2];
    float* sr = scal + (size_t)row * 384;
    sr[u]       = rna_tf32(s);
    sr[128 + u] = rna_tf32(s * s);
    sr[256 + u] = rna_tf32(v0 * v0 + v1 * v1 + v2 * v2);
}

// ---------------------------------------------------------------------------
// TF32 mma.sync GEMM, pipelined:
//   C[M, ncols*128] = A[M,K] @ Bp^T, Bp packed [N,K] row-major (K-major).
// Block 128x128, BK=16, 3-stage cp.async. 128 threads = 4 warps (2x2 grid of
// 64x64 warp tiles). Warp tile = 4x8 m16n8k8 atoms x 2 k-steps.
// smem per stage: A[128][20] + B[128][20] floats (pad 4 -> conflict-free).
// blockIdx.x = column tile (fast -> L2 reuse of A panel), blockIdx.y = row tile,
// blockIdx.z = batch plane. EPI: 0 none, 1 silu, 2 silu+tf32-round.
// Requires K % 16 == 0, 16B-aligned pointers, N covered exactly by 128-tiles.
// ---------------------------------------------------------------------------
#define STAGE_WORDS 5120            // (128*20)*2 tiles
#define TILE_WORDS  2560            // 128*20

template <int EPI>
__global__ __launch_bounds__(128) void gemm_mma_kernel(
    const float* __restrict__ A, int lda, long long bsA,
    const float* __restrict__ Bp,
    float* __restrict__ C, int ldc, long long bsC,
    int M, int K)
{
    extern __shared__ float smf[];
    const uint32_t sb = smem_u32(smf);

    A += (size_t)blockIdx.z * bsA;
    C += (size_t)blockIdx.z * bsC;

    const int tid  = threadIdx.x;
    const int w    = tid >> 5;
    const int lane = tid & 31;
    const int g    = lane >> 2;       // 0..7
    const int tg   = lane & 3;        // 0..3
    const int wm   = (w & 1) * 64;
    const int wn   = (w >> 1) * 64;
    const int rowBase = blockIdx.y * 128;
    const int colBase = blockIdx.x * 128;
    const int T = K >> 4;             // BK=16 steps

    // Stage loader: A rows [rowBase..+128) x k0..k0+16, B rows [colBase..+128).
    auto load_stage = [&](int s, int kt) {
        const int k0 = kt << 4;
        const uint32_t ab = sb + (uint32_t)(s * STAGE_WORDS) * 4u;
        const uint32_t bb = ab + TILE_WORDS * 4u;
#pragma unroll
        for (int i = 0; i < 4; i++) {
            int flat = i * 128 + tid;        // 0..511
            int r = flat >> 2;               // 0..127
            int c = flat & 3;                // 16B chunk (4 floats)
            uint32_t so = (uint32_t)(r * 20 + c * 4) * 4u;
            int gr = rowBase + r;
            const float* srcA = A + (size_t)(gr < M ? gr : 0) * lda + k0 + c * 4;
            cp16(ab + so, srcA, gr < M ? 16 : 0);
            const float* srcB = Bp + (size_t)(colBase + r) * K + k0 + c * 4;
            cp16(bb + so, srcB, 16);
        }
        asm volatile("cp.async.commit_group;" ::: "memory");
    };

    float acc[4][8][4];
#pragma unroll
    for (int mt = 0; mt < 4; mt++)
#pragma unroll
        for (int nt = 0; nt < 8; nt++)
#pragma unroll
            for (int i = 0; i < 4; i++) acc[mt][nt][i] = 0.0f;

    load_stage(0, 0);
    load_stage(1, 1);

    for (int kt = 0; kt < T; kt++) {
        const int s = kt % 3;
        if (kt + 1 < T) asm volatile("cp.async.wait_group 1;" ::: "memory");
        else            asm volatile("cp.async.wait_group 0;" ::: "memory");
        __syncthreads();
        if (kt + 2 < T) load_stage((kt + 2) % 3, kt + 2);

        const float* as = smf + s * STAGE_WORDS;
        const float* bs = as + TILE_WORDS;
#pragma unroll
        for (int kf = 0; kf < 2; kf++) {
            const int kb = kf * 8;
            unsigned a[4][4], b[8][2];
#pragma unroll
            for (int mt = 0; mt < 4; mt++) {
                const unsigned* ap = reinterpret_cast<const unsigned*>(
                    as + (wm + mt * 16 + g) * 20 + kb + tg);
                a[mt][0] = ap[0];
                a[mt][1] = ap[8 * 20];
                a[mt][2] = ap[4];
                a[mt][3] = ap[8 * 20 + 4];
            }
#pragma unroll
            for (int nt = 0; nt < 8; nt++) {
                const unsigned* bp = reinterpret_cast<const unsigned*>(
                    bs + (wn + nt * 8 + g) * 20 + kb + tg);
                b[nt][0] = bp[0];
                b[nt][1] = bp[4];
            }
#pragma unroll
            for (int mt = 0; mt < 4; mt++)
#pragma unroll
                for (int nt = 0; nt < 8; nt++) {
                    asm volatile(
                        "mma.sync.aligned.m16n8k8.row.col.f32.tf32.tf32.f32 "
                        "{%0,%1,%2,%3}, {%4,%5,%6,%7}, {%8,%9}, {%0,%1,%2,%3};\n"
                        : "+f"(acc[mt][nt][0]), "+f"(acc[mt][nt][1]),
                          "+f"(acc[mt][nt][2]), "+f"(acc[mt][nt][3])
                        : "r"(a[mt][0]), "r"(a[mt][1]), "r"(a[mt][2]), "r"(a[mt][3]),
                          "r"(b[nt][0]), "r"(b[nt][1]));
                }
        }
        __syncthreads();
    }

    // Epilogue: c0/c1 at (row, 2tg), c2/c3 at (row+8, 2tg).
#pragma unroll
    for (int mt = 0; mt < 4; mt++) {
        int r0 = rowBase + wm + mt * 16 + g;
#pragma unroll
        for (int nt = 0; nt < 8; nt++) {
            int c0 = colBase + wn + nt * 8 + 2 * tg;
            float2 lo = make_float2(acc[mt][nt][0], acc[mt][nt][1]);
            float2 hi = make_float2(acc[mt][nt][2], acc[mt][nt][3]);
            if (EPI >= 1) {
                lo.x = silu_f(lo.x); lo.y = silu_f(lo.y);
                hi.x = silu_f(hi.x); hi.y = silu_f(hi.y);
            }
            if (EPI == 2) {
                lo.x = rna_tf32(lo.x); lo.y = rna_tf32(lo.y);
                hi.x = rna_tf32(hi.x); hi.y = rna_tf32(hi.y);
            }
            if (r0 < M)
                *reinterpret_cast<float2*>(C + (size_t)r0 * ldc + c0) = lo;
            if (r0 + 8 < M)
                *reinterpret_cast<float2*>(C + (size_t)(r0 + 8) * ldc + c0) = hi;
        }
    }
}

// ---------------------------------------------------------------------------
// K4: gate scal in place and build gated vec planes (tf32-rounded outputs).
// ---------------------------------------------------------------------------
__global__ void gate_prep_kernel(const float* __restrict__ x, const float* __restrict__ gates,
                                 float* __restrict__ scal, float* __restrict__ vg, int n) {
    int idx = blockIdx.x * blockDim.x + threadIdx.x;
    if (idx >= n * 384) return;
    int row = idx / 384;
    int j = idx - row * 384;
    const float* g = gates + (size_t)row * 640;
    scal[idx] = rna_tf32(scal[idx] * g[j]);
    if (j < 128) {
        int u = j;
        const float* xr = x + (size_t)row * 512;
        float s  = xr[u];
        float g1 = g[384 + u];
        float c2 = SQ2F * s * g[512 + u];
#pragma unroll
        for (int i = 0; i < 3; i++) {
            float vi = xr[128 + u * 3 + i];
            float* vgp = vg + ((size_t)i * n + row) * 256;
            vgp[u]       = rna_tf32(vi * g1);
            vgp[128 + u] = rna_tf32(vi * c2);
        }
    }
}

// ---------------------------------------------------------------------------
// K7: residuals + scalar layernorm + vector RMS norm, write output [n,512].
// ---------------------------------------------------------------------------
__global__ void finalize_kernel(const float* __restrict__ x, const float* __restrict__ outs,
                                const float* __restrict__ outv, float* __restrict__ out, int n) {
    int gw = (int)((blockIdx.x * blockDim.x + threadIdx.x) >> 5);
    int lane = threadIdx.x & 31;
    if (gw >= n) return;
    const float* xr = x + (size_t)gw * 512;
    float* orow = out + (size_t)gw * 512;

    float so[4];
    float sum = 0.f;
#pragma unroll
    for (int t = 0; t < 4; t++) {
        int u = lane + 32 * t;
        so[t] = outs[(size_t)gw * 128 + u] + xr[u];
        sum += so[t];
    }
#pragma unroll
    for (int o = 16; o > 0; o >>= 1) sum += __shfl_xor_sync(0xffffffffu, sum, o);
    float mean = sum * (1.0f / 128.0f);
    float ssum = 0.f;
#pragma unroll
    for (int t = 0; t < 4; t++) {
        so[t] -= mean;
        ssum += so[t] * so[t];
    }
#pragma unroll
    for (int o = 16; o > 0; o >>= 1) ssum += __shfl_xor_sync(0xffffffffu, ssum, o);
    float inv = 1.0f / (sqrtf(ssum * (1.0f / 128.0f)) + 1e-6f);
#pragma unroll
    for (int t = 0; t < 4; t++) orow[lane + 32 * t] = so[t] * inv;

    float vo[4][3];
    float vs = 0.f;
#pragma unroll
    for (int t = 0; t < 4; t++) {
        int u = lane + 32 * t;
#pragma unroll
        for (int i = 0; i < 3; i++) {
            vo[t][i] = outv[((size_t)i * n + gw) * 128 + u] + xr[128 + u * 3 + i];
            vs += vo[t][i] * vo[t][i];
        }
    }
#pragma unroll
    for (int o = 16; o > 0; o >>= 1) vs += __shfl_xor_sync(0xffffffffu, vs, o);
    float vinv = 1.0f / (sqrtf(vs * (1.0f / 128.0f)) + 1e-6f);
#pragma unroll
    for (int t = 0; t < 4; t++) {
        int u = lane + 32 * t;
#pragma unroll
        for (int i = 0; i < 3; i++)
            orow[128 + u * 3 + i] = vo[t][i] * vinv;
    }
}

// ---------------------------------------------------------------------------
extern "C" void kernel_launch(void* const* d_in, const int* in_sizes, int n_in,
                              void* d_out, int out_size) {
    const float* x  = (const float*)d_in[0];
    const float* W1 = (const float*)d_in[1];   // [384,384]
    const float* W2 = (const float*)d_in[2];   // [384,768] (cols 640:768 dead)
    const float* Ws = (const float*)d_in[3];   // [384,128]
    const float* Wv = (const float*)d_in[4];   // [256,128]
    float* out = (float*)d_out;
    int n = in_sizes[0] / 512;

    float *scal, *h, *gates, *vg, *outs, *outv, *w1p, *w2p, *wsp, *wvp;
    cudaGetSymbolAddress((void**)&scal,  g_scal);
    cudaGetSymbolAddress((void**)&h,     g_h);
    cudaGetSymbolAddress((void**)&gates, g_gates);
    cudaGetSymbolAddress((void**)&vg,    g_vg);
    cudaGetSymbolAddress((void**)&outs,  g_outs);
    cudaGetSymbolAddress((void**)&outv,  g_outv);
    cudaGetSymbolAddress((void**)&w1p,   g_w1p);
    cudaGetSymbolAddress((void**)&w2p,   g_w2p);
    cudaGetSymbolAddress((void**)&wsp,   g_wsp);
    cudaGetSymbolAddress((void**)&wvp,   g_wvp);

    const int SMEM_BYTES = 3 * STAGE_WORDS * 4;   // 61440
    cudaFuncSetAttribute(gemm_mma_kernel<0>, cudaFuncAttributeMaxDynamicSharedMemorySize, SMEM_BYTES);
    cudaFuncSetAttribute(gemm_mma_kernel<1>, cudaFuncAttributeMaxDynamicSharedMemorySize, SMEM_BYTES);
    cudaFuncSetAttribute(gemm_mma_kernel<2>, cudaFuncAttributeMaxDynamicSharedMemorySize, SMEM_BYTES);

    int mblocks = (n + 127) / 128;

    // Pack weights -> [N,K] K-major, tf32-rounded.
    pack_w_kernel<<<(384 * 384 + 255) / 256, 256>>>(W1, w1p, 384, 384, 384);
    pack_w_kernel<<<(640 * 384 + 255) / 256, 256>>>(W2, w2p, 384, 640, 768);
    pack_w_kernel<<<(128 * 384 + 255) / 256, 256>>>(Ws, wsp, 384, 128, 128);
    pack_w_kernel<<<(128 * 256 + 255) / 256, 256>>>(Wv, wvp, 256, 128, 128);

    // K1: scal features (tf32-rounded)
    prep_scal_kernel<<<(n * 128 + 255) / 256, 256>>>(x, scal, n);

    // G1: h = silu(scal @ W1), tf32-rounded output (feeds G2)
    dim3 g1(3, mblocks, 1);
    gemm_mma_kernel<2><<<g1, 128, SMEM_BYTES>>>(scal, 384, 0LL, w1p, h, 384, 0LL, n, 384);

    // G2: gates = silu(h @ W2[:, :640])
    dim3 g2(5, mblocks, 1);
    gemm_mma_kernel<1><<<g2, 128, SMEM_BYTES>>>(h, 384, 0LL, w2p, gates, 640, 0LL, n, 384);

    // K4: gate scal in-place, build vg planes (tf32-rounded)
    gate_prep_kernel<<<(n * 384 + 255) / 256, 256>>>(x, gates, scal, vg, n);

    // G5: outs = scal_gated @ Ws
    dim3 g5(1, mblocks, 1);
    gemm_mma_kernel<0><<<g5, 128, SMEM_BYTES>>>(scal, 384, 0LL, wsp, outs, 128, 0LL, n, 384);

    // G6: outv_i = vg_i @ Wv  (3 planes over z)
    dim3 g6(1, mblocks, 3);
    gemm_mma_kernel<0><<<g6, 128, SMEM_BYTES>>>(vg, 256, (long long)n * 256, wvp,
                                                outv, 128, (long long)n * 128, n, 256);

    // K7: residual + norms + output
    finalize_kernel<<<(n + 7) / 8, 256>>>(x, outs, outv, out, n);
}

// round 6
// speedup vs baseline: 3.5138x; 1.4206x over previous
#include <cuda_runtime.h>
#include <cuda_fp16.h>
#include <math.h>
#include <stdint.h>

// Problem constants: N rows up to 100000, MUL=128, x row = 512 floats.
#define MAXN 100000
#define SQ2F 1.41421356237309515f

// Scratch (allocation-free rule: __device__ globals). fp16 for GEMM-facing data.
__device__ __half g_scal [(size_t)MAXN * 384];
__device__ __half g_h    [(size_t)MAXN * 384];
__device__ __half g_gates[(size_t)MAXN * 640];
__device__ __half g_vg   [(size_t)MAXN * 256 * 3];
__device__ float  g_outs [(size_t)MAXN * 128];
__device__ float  g_outv [(size_t)MAXN * 128 * 3];
// Packed (transposed to [N,K] K-major, fp16) weights.
__device__ __half g_w1p[384 * 384];
__device__ __half g_w2p[640 * 384];
__device__ __half g_wsp[128 * 384];
__device__ __half g_wvp[128 * 256];

__device__ __forceinline__ float silu_f(float v) { return v / (1.0f + expf(-v)); }

__device__ __forceinline__ uint32_t smem_u32(const void* p) {
    uint32_t a;
    asm("{ .reg .u64 t; cvta.to.shared.u64 t, %1; cvt.u32.u64 %0, t; }" : "=r"(a) : "l"(p));
    return a;
}

__device__ __forceinline__ void cp16(uint32_t dst, const void* src, int sz) {
    asm volatile("cp.async.cg.shared.global [%0], [%1], 16, %2;"
                 :: "r"(dst), "l"(src), "r"(sz) : "memory");
}

// ---------------------------------------------------------------------------
// Weight pack: Wp[n*K + k] = fp16(W[k*ldw + n]); keep first Ncols columns.
// ---------------------------------------------------------------------------
__global__ void pack_w_kernel(const float* __restrict__ W, __half* __restrict__ Wp,
                              int K, int Ncols, int ldw) {
    int idx = blockIdx.x * blockDim.x + threadIdx.x;
    if (idx >= Ncols * K) return;
    int n = idx / K;
    int k = idx - n * K;
    Wp[idx] = __float2half(W[(size_t)k * ldw + n]);
}

// ---------------------------------------------------------------------------
// K1: scal[n,384] = [s, s*s, |v|^2] in fp16 (GEMM input precision).
// ---------------------------------------------------------------------------
__global__ void prep_scal_kernel(const float* __restrict__ x, __half* __restrict__ scal, int n) {
    int idx = blockIdx.x * blockDim.x + threadIdx.x;
    if (idx >= n * 128) return;
    int row = idx >> 7;
    int u = idx & 127;
    const float* xr = x + (size_t)row * 512;
    float s  = xr[u];
    float v0 = xr[128 + u * 3 + 0];
    float v1 = xr[128 + u * 3 + 1];
    float v2 = xr[128 + u * 3 + 2];
    __half* sr = scal + (size_t)row * 384;
    sr[u]       = __float2half(s);
    sr[128 + u] = __float2half(s * s);
    sr[256 + u] = __float2half(v0 * v0 + v1 * v1 + v2 * v2);
}

// ---------------------------------------------------------------------------
// FP16 mma.sync GEMM (fp32 accumulate), pipelined:
//   C[M, ncols*128] = A[M,K] @ Bp^T, Bp packed [N,K] row-major (K contiguous).
// Block 128x128, BK=32, 3-stage cp.async. 128 threads = 4 warps (2x2 grid of
// 64x64 warp tiles); warp tile = 4x8 m16n8k16 atoms x 2 k16-steps per BK.
// smem per stage/tile: 128 rows x 40 halves (pad 8 -> conflict-free LDS.32).
// blockIdx.x = col tile (fast -> A panel L2 reuse), y = row tile, z = batch.
// SILU: apply silu in epilogue. OT: __half (GEMM-chain) or float (outputs).
// Requires K % 32 == 0, 16B-aligned pointers, N covered exactly by 128-tiles.
// ---------------------------------------------------------------------------
#define TILE_HALVES 5120            // 128*40
#define STAGE_HALVES 10240          // A tile + B tile

template <bool SILU, typename OT>
__global__ __launch_bounds__(128) void gemm_fp16_kernel(
    const __half* __restrict__ A, int lda, long long bsA,
    const __half* __restrict__ Bp,
    OT* __restrict__ C, int ldc, long long bsC,
    int M, int K)
{
    extern __shared__ __half smh[];
    const uint32_t sb = smem_u32(smh);

    A += (size_t)blockIdx.z * bsA;
    C += (size_t)blockIdx.z * bsC;

    const int tid  = threadIdx.x;
    const int w    = tid >> 5;
    const int lane = tid & 31;
    const int g    = lane >> 2;       // 0..7
    const int tg   = lane & 3;        // 0..3
    const int wm   = (w & 1) * 64;
    const int wn   = (w >> 1) * 64;
    const int rowBase = blockIdx.y * 128;
    const int colBase = blockIdx.x * 128;
    const int T = K >> 5;             // BK=32 steps

    // Stage loader: A rows [rowBase..+128) x halves k0..k0+32; B same for cols.
    auto load_stage = [&](int s, int kt) {
        const int k0 = kt << 5;
        const uint32_t ab = sb + (uint32_t)(s * STAGE_HALVES) * 2u;
        const uint32_t bb = ab + TILE_HALVES * 2u;
#pragma unroll
        for (int i = 0; i < 4; i++) {
            int flat = i * 128 + tid;        // 0..511
            int r = flat >> 2;               // 0..127
            int c = flat & 3;                // chunk of 8 halves (16B)
            uint32_t so = (uint32_t)(r * 40 + c * 8) * 2u;
            int gr = rowBase + r;
            const __half* srcA = A + (size_t)(gr < M ? gr : 0) * lda + k0 + c * 8;
            cp16(ab + so, srcA, gr < M ? 16 : 0);
            const __half* srcB = Bp + (size_t)(colBase + r) * K + k0 + c * 8;
            cp16(bb + so, srcB, 16);
        }
        asm volatile("cp.async.commit_group;" ::: "memory");
    };

    float acc[4][8][4];
#pragma unroll
    for (int mt = 0; mt < 4; mt++)
#pragma unroll
        for (int nt = 0; nt < 8; nt++)
#pragma unroll
            for (int i = 0; i < 4; i++) acc[mt][nt][i] = 0.0f;

    load_stage(0, 0);
    load_stage(1, 1);

    for (int kt = 0; kt < T; kt++) {
        const int s = kt % 3;
        if (kt + 1 < T) asm volatile("cp.async.wait_group 1;" ::: "memory");
        else            asm volatile("cp.async.wait_group 0;" ::: "memory");
        __syncthreads();
        if (kt + 2 < T) load_stage((kt + 2) % 3, kt + 2);

        // 32-bit word views; row stride = 20 words (40 halves).
        const uint32_t* aw = reinterpret_cast<const uint32_t*>(smh + s * STAGE_HALVES);
        const uint32_t* bw = aw + (TILE_HALVES / 2);
#pragma unroll
        for (int kf = 0; kf < 2; kf++) {
            const int kb = kf * 8;           // word offset of this k16 step
            unsigned a[4][4], b[8][2];
#pragma unroll
            for (int mt = 0; mt < 4; mt++) {
                const uint32_t* ap = aw + (wm + mt * 16 + g) * 20 + kb + tg;
                a[mt][0] = ap[0];
                a[mt][1] = ap[8 * 20];
                a[mt][2] = ap[4];
                a[mt][3] = ap[8 * 20 + 4];
            }
#pragma unroll
            for (int nt = 0; nt < 8; nt++) {
                const uint32_t* bp = bw + (wn + nt * 8 + g) * 20 + kb + tg;
                b[nt][0] = bp[0];
                b[nt][1] = bp[4];
            }
#pragma unroll
            for (int mt = 0; mt < 4; mt++)
#pragma unroll
                for (int nt = 0; nt < 8; nt++) {
                    asm volatile(
                        "mma.sync.aligned.m16n8k16.row.col.f32.f16.f16.f32 "
                        "{%0,%1,%2,%3}, {%4,%5,%6,%7}, {%8,%9}, {%0,%1,%2,%3};\n"
                        : "+f"(acc[mt][nt][0]), "+f"(acc[mt][nt][1]),
                          "+f"(acc[mt][nt][2]), "+f"(acc[mt][nt][3])
                        : "r"(a[mt][0]), "r"(a[mt][1]), "r"(a[mt][2]), "r"(a[mt][3]),
                          "r"(b[nt][0]), "r"(b[nt][1]));
                }
        }
        __syncthreads();
    }

    // Epilogue: c0/c1 at (row, 2tg..+1), c2/c3 at (row+8, 2tg..+1).
#pragma unroll
    for (int mt = 0; mt < 4; mt++) {
        int r0 = rowBase + wm + mt * 16 + g;
#pragma unroll
        for (int nt = 0; nt < 8; nt++) {
            int c0 = colBase + wn + nt * 8 + 2 * tg;
            float2 lo = make_float2(acc[mt][nt][0], acc[mt][nt][1]);
            float2 hi = make_float2(acc[mt][nt][2], acc[mt][nt][3]);
            if (SILU) {
                lo.x = silu_f(lo.x); lo.y = silu_f(lo.y);
                hi.x = silu_f(hi.x); hi.y = silu_f(hi.y);
            }
            if (r0 < M) {
                OT* cr = C + (size_t)r0 * ldc + c0;
                if (sizeof(OT) == 2) *reinterpret_cast<__half2*>(cr) = __float22half2_rn(lo);
                else                 *reinterpret_cast<float2*>(cr) = lo;
            }
            if (r0 + 8 < M) {
                OT* cr = C + (size_t)(r0 + 8) * ldc + c0;
                if (sizeof(OT) == 2) *reinterpret_cast<__half2*>(cr) = __float22half2_rn(hi);
                else                 *reinterpret_cast<float2*>(cr) = hi;
            }
        }
    }
}

// ---------------------------------------------------------------------------
// K4: gate scal in place and build gated vec planes (fp16 in/out).
// ---------------------------------------------------------------------------
__global__ void gate_prep_kernel(const float* __restrict__ x, const __half* __restrict__ gates,
                                 __half* __restrict__ scal, __half* __restrict__ vg, int n) {
    int idx = blockIdx.x * blockDim.x + threadIdx.x;
    if (idx >= n * 384) return;
    int row = idx / 384;
    int j = idx - row * 384;
    const __half* g = gates + (size_t)row * 640;
    scal[idx] = __float2half(__half2float(scal[idx]) * __half2float(g[j]));
    if (j < 128) {
        int u = j;
        const float* xr = x + (size_t)row * 512;
        float s  = xr[u];
        float g1 = __half2float(g[384 + u]);
        float c2 = SQ2F * s * __half2float(g[512 + u]);
#pragma unroll
        for (int i = 0; i < 3; i++) {
            float vi = xr[128 + u * 3 + i];
            __half* vgp = vg + ((size_t)i * n + row) * 256;
            vgp[u]       = __float2half(vi * g1);
            vgp[128 + u] = __float2half(vi * c2);
        }
    }
}

// ---------------------------------------------------------------------------
// K7: residuals + scalar layernorm + vector RMS norm, write output [n,512].
// ---------------------------------------------------------------------------
__global__ void finalize_kernel(const float* __restrict__ x, const float* __restrict__ outs,
                                const float* __restrict__ outv, float* __restrict__ out, int n) {
    int gw = (int)((blockIdx.x * blockDim.x + threadIdx.x) >> 5);
    int lane = threadIdx.x & 31;
    if (gw >= n) return;
    const float* xr = x + (size_t)gw * 512;
    float* orow = out + (size_t)gw * 512;

    float so[4];
    float sum = 0.f;
#pragma unroll
    for (int t = 0; t < 4; t++) {
        int u = lane + 32 * t;
        so[t] = outs[(size_t)gw * 128 + u] + xr[u];
        sum += so[t];
    }
#pragma unroll
    for (int o = 16; o > 0; o >>= 1) sum += __shfl_xor_sync(0xffffffffu, sum, o);
    float mean = sum * (1.0f / 128.0f);
    float ssum = 0.f;
#pragma unroll
    for (int t = 0; t < 4; t++) {
        so[t] -= mean;
        ssum += so[t] * so[t];
    }
#pragma unroll
    for (int o = 16; o > 0; o >>= 1) ssum += __shfl_xor_sync(0xffffffffu, ssum, o);
    float inv = 1.0f / (sqrtf(ssum * (1.0f / 128.0f)) + 1e-6f);
#pragma unroll
    for (int t = 0; t < 4; t++) orow[lane + 32 * t] = so[t] * inv;

    float vo[4][3];
    float vs = 0.f;
#pragma unroll
    for (int t = 0; t < 4; t++) {
        int u = lane + 32 * t;
#pragma unroll
        for (int i = 0; i < 3; i++) {
            vo[t][i] = outv[((size_t)i * n + gw) * 128 + u] + xr[128 + u * 3 + i];
            vs += vo[t][i] * vo[t][i];
        }
    }
#pragma unroll
    for (int o = 16; o > 0; o >>= 1) vs += __shfl_xor_sync(0xffffffffu, vs, o);
    float vinv = 1.0f / (sqrtf(vs * (1.0f / 128.0f)) + 1e-6f);
#pragma unroll
    for (int t = 0; t < 4; t++) {
        int u = lane + 32 * t;
#pragma unroll
        for (int i = 0; i < 3; i++)
            orow[128 + u * 3 + i] = vo[t][i] * vinv;
    }
}

// ---------------------------------------------------------------------------
extern "C" void kernel_launch(void* const* d_in, const int* in_sizes, int n_in,
                              void* d_out, int out_size) {
    const float* x  = (const float*)d_in[0];
    const float* W1 = (const float*)d_in[1];   // [384,384]
    const float* W2 = (const float*)d_in[2];   // [384,768] (cols 640:768 dead)
    const float* Ws = (const float*)d_in[3];   // [384,128]
    const float* Wv = (const float*)d_in[4];   // [256,128]
    float* out = (float*)d_out;
    int n = in_sizes[0] / 512;

    __half *scal, *h, *gates, *vg, *w1p, *w2p, *wsp, *wvp;
    float *outs, *outv;
    cudaGetSymbolAddress((void**)&scal,  g_scal);
    cudaGetSymbolAddress((void**)&h,     g_h);
    cudaGetSymbolAddress((void**)&gates, g_gates);
    cudaGetSymbolAddress((void**)&vg,    g_vg);
    cudaGetSymbolAddress((void**)&outs,  g_outs);
    cudaGetSymbolAddress((void**)&outv,  g_outv);
    cudaGetSymbolAddress((void**)&w1p,   g_w1p);
    cudaGetSymbolAddress((void**)&w2p,   g_w2p);
    cudaGetSymbolAddress((void**)&wsp,   g_wsp);
    cudaGetSymbolAddress((void**)&wvp,   g_wvp);

    const int SMEM_BYTES = 3 * STAGE_HALVES * 2;   // 61440
    cudaFuncSetAttribute(gemm_fp16_kernel<true, __half>,
                         cudaFuncAttributeMaxDynamicSharedMemorySize, SMEM_BYTES);
    cudaFuncSetAttribute(gemm_fp16_kernel<false, float>,
                         cudaFuncAttributeMaxDynamicSharedMemorySize, SMEM_BYTES);

    int mblocks = (n + 127) / 128;

    // Pack weights -> [N,K] K-major fp16.
    pack_w_kernel<<<(384 * 384 + 255) / 256, 256>>>(W1, w1p, 384, 384, 384);
    pack_w_kernel<<<(640 * 384 + 255) / 256, 256>>>(W2, w2p, 384, 640, 768);
    pack_w_kernel<<<(128 * 384 + 255) / 256, 256>>>(Ws, wsp, 384, 128, 128);
    pack_w_kernel<<<(128 * 256 + 255) / 256, 256>>>(Wv, wvp, 256, 128, 128);

    // K1: scal features (fp16)
    prep_scal_kernel<<<(n * 128 + 255) / 256, 256>>>(x, scal, n);

    // G1: h = silu(scal @ W1) -> fp16
    dim3 g1(3, mblocks, 1);
    gemm_fp16_kernel<true, __half><<<g1, 128, SMEM_BYTES>>>(
        scal, 384, 0LL, w1p, h, 384, 0LL, n, 384);

    // G2: gates = silu(h @ W2[:, :640]) -> fp16
    dim3 g2(5, mblocks, 1);
    gemm_fp16_kernel<true, __half><<<g2, 128, SMEM_BYTES>>>(
        h, 384, 0LL, w2p, gates, 640, 0LL, n, 384);

    // K4: gate scal in-place, build vg planes
    gate_prep_kernel<<<(n * 384 + 255) / 256, 256>>>(x, gates, scal, vg, n);

    // G5: outs = scal_gated @ Ws -> fp32
    dim3 g5(1, mblocks, 1);
    gemm_fp16_kernel<false, float><<<g5, 128, SMEM_BYTES>>>(
        scal, 384, 0LL, wsp, outs, 128, 0LL, n, 384);

    // G6: outv_i = vg_i @ Wv (3 planes over z) -> fp32
    dim3 g6(1, mblocks, 3);
    gemm_fp16_kernel<false, float><<<g6, 128, SMEM_BYTES>>>(
        vg, 256, (long long)n * 256, wvp, outv, 128, (long long)n * 128, n, 256);

    // K7: residual + norms + output
    finalize_kernel<<<(n + 7) / 8, 256>>>(x, outs, outv, out, n);
}